// round 1
// baseline (speedup 1.0000x reference)
#include <cuda_runtime.h>
#include <math.h>

#define Bq 8
#define Tq 4096
#define Dq 768
#define Hq 12
#define HDq 64
#define Kq 32
#define NSEG 32
#define MROWS 256   // B*K

typedef unsigned long long ull;

// ---------- scratch (device globals; no runtime allocation) ----------
__device__ float g_part[(size_t)NSEG * MROWS * Dq];  // T-split partials of xs
__device__ float g_xs  [(size_t)MROWS * Dq];          // xs = basis^T x   [256,768]
__device__ float g_qkv [(size_t)MROWS * 3 * Dq];      // qkv_spec         [256,2304]
__device__ float g_vs  [(size_t)MROWS * Dq];          // fhn-scaled v_spec[256,768]
__device__ float g_y   [(size_t)MROWS * Dq];          // (fhn*v_spec)@Wout^T [256,768]

// ---------- packed f32x2 helpers ----------
__device__ __forceinline__ ull ffma2(ull a, ull b, ull c) {
    ull d;
    asm("fma.rn.f32x2 %0, %1, %2, %3;" : "=l"(d) : "l"(a), "l"(b), "l"(c));
    return d;
}
__device__ __forceinline__ ull fadd2(ull a, ull b) {
    ull d;
    asm("add.rn.f32x2 %0, %1, %2;" : "=l"(d) : "l"(a), "l"(b));
    return d;
}
__device__ __forceinline__ ull pack2(float v) {
    ull r; unsigned u = __float_as_uint(v);
    asm("mov.b64 %0, {%1, %2};" : "=l"(r) : "r"(u), "r"(u));
    return r;
}

// ======================================================================
// Kernel A: partial xs[seg][b,k,d] = sum_{t in seg} basis[b,t,k] * x[b,t,d]
// block = 384 threads, each thread owns a d-pair (f32x2), all 32 k in regs.
// ======================================================================
__global__ __launch_bounds__(384, 2) void kA(const float* __restrict__ x,
                                             const float* __restrict__ basis) {
    const int b = blockIdx.y, seg = blockIdx.x;
    const int tid = threadIdx.x;
    __shared__ ull sb[64][Kq];  // basis values duplicated into f32x2 pairs

    ull acc[Kq];
#pragma unroll
    for (int k = 0; k < Kq; ++k) acc[k] = 0ull;

    const int TSEG = Tq / NSEG;  // 128
    const int t0 = seg * TSEG;
    const ull* x2 = (const ull*)x + (size_t)b * Tq * (Dq / 2);

    for (int tile = 0; tile < TSEG / 64; ++tile) {
        const int tb = t0 + tile * 64;
        __syncthreads();
        for (int i = tid; i < 64 * Kq; i += 384) {
            int tt = i >> 5, k = i & 31;
            sb[tt][k] = pack2(basis[((size_t)b * Tq + tb + tt) * Kq + k]);
        }
        __syncthreads();
        for (int tt = 0; tt < 64; ++tt) {
            ull xv = x2[(size_t)(tb + tt) * (Dq / 2) + tid];
            const ulonglong2* bp = (const ulonglong2*)sb[tt];
#pragma unroll
            for (int k2 = 0; k2 < 16; ++k2) {
                ulonglong2 bb = bp[k2];
                acc[2 * k2]     = ffma2(xv, bb.x, acc[2 * k2]);
                acc[2 * k2 + 1] = ffma2(xv, bb.y, acc[2 * k2 + 1]);
            }
        }
    }
    ull* po = (ull*)g_part + ((size_t)seg * MROWS + b * Kq) * (Dq / 2) + tid;
#pragma unroll
    for (int k = 0; k < Kq; ++k) po[(size_t)k * (Dq / 2)] = acc[k];
}

// ======================================================================
// Kernel A2: reduce NSEG partials -> g_xs
// ======================================================================
__global__ void kA2() {
    const int j = blockIdx.x * 256 + threadIdx.x;  // over MROWS*Dq = 196608
    float s = 0.f;
#pragma unroll
    for (int seg = 0; seg < NSEG; ++seg)
        s += g_part[(size_t)seg * (MROWS * Dq) + j];
    g_xs[j] = s;
}

// ======================================================================
// Generic fp32 GEMM  C[M=256,N] = A[256,768] * W[N,768]^T
// 64x64 block tile, 256 threads, 4m x 4n microtile via 8 FFMA2/k-step.
// mode 0: A=g_xs, C=g_qkv ; mode 1: A=g_vs, C=g_y
// ======================================================================
__global__ __launch_bounds__(256, 2) void kgemm(const float* __restrict__ Wm,
                                                int N, int mode) {
    const float* Am = (mode == 0) ? g_xs : g_vs;
    float*       Cm = (mode == 0) ? g_qkv : g_y;

    __shared__ __align__(16) float As[16][64];
    __shared__ __align__(16) float Bs[16][64];

    const int tid = threadIdx.x;
    const int bm = blockIdx.y * 64, bn = blockIdx.x * 64;
    const int tm = (tid >> 4) << 2, tn = (tid & 15) << 2;

    ull acc[4][2];
#pragma unroll
    for (int i = 0; i < 4; ++i) { acc[i][0] = 0ull; acc[i][1] = 0ull; }

    const int lrow = tid >> 2;          // 0..63
    const int lq   = (tid & 3) << 2;    // 0,4,8,12
    const float* Ag = Am + (size_t)(bm + lrow) * 768 + lq;
    const float* Bg = Wm + (size_t)(bn + lrow) * 768 + lq;

    for (int kt = 0; kt < 768; kt += 16) {
        float4 av = *(const float4*)(Ag + kt);
        float4 bv = *(const float4*)(Bg + kt);
        __syncthreads();
        As[lq + 0][lrow] = av.x; As[lq + 1][lrow] = av.y;
        As[lq + 2][lrow] = av.z; As[lq + 3][lrow] = av.w;
        Bs[lq + 0][lrow] = bv.x; Bs[lq + 1][lrow] = bv.y;
        Bs[lq + 2][lrow] = bv.z; Bs[lq + 3][lrow] = bv.w;
        __syncthreads();
#pragma unroll
        for (int k = 0; k < 16; ++k) {
            float4 af = *(const float4*)&As[k][tm];
            ulonglong2 bf = *(const ulonglong2*)&Bs[k][tn];
            ull a0 = pack2(af.x), a1 = pack2(af.y), a2 = pack2(af.z), a3 = pack2(af.w);
            acc[0][0] = ffma2(a0, bf.x, acc[0][0]); acc[0][1] = ffma2(a0, bf.y, acc[0][1]);
            acc[1][0] = ffma2(a1, bf.x, acc[1][0]); acc[1][1] = ffma2(a1, bf.y, acc[1][1]);
            acc[2][0] = ffma2(a2, bf.x, acc[2][0]); acc[2][1] = ffma2(a2, bf.y, acc[2][1]);
            acc[3][0] = ffma2(a3, bf.x, acc[3][0]); acc[3][1] = ffma2(a3, bf.y, acc[3][1]);
        }
    }
#pragma unroll
    for (int i = 0; i < 4; ++i) {
        ulonglong2 r; r.x = acc[i][0]; r.y = acc[i][1];
        *(ulonglong2*)(Cm + (size_t)(bm + tm + i) * N + bn + tn) = r;
    }
}

// ======================================================================
// Kernel B2: attn dot + filter + FHN dynamics + scale v_spec -> g_vs
// one block (64 threads) per (b,k,h)
// ======================================================================
__global__ void kfhn(const float* __restrict__ sfilt) {
    const int h = blockIdx.x;        // 0..11
    const int m = blockIdx.y;        // b*32+k
    const int k = m & 31;
    const int t = threadIdx.x;       // 0..63 (head dim)
    const float* row = g_qkv + (size_t)m * (3 * Dq);

    float qv = row[h * HDq + t];
    float kv = row[Dq + h * HDq + t];
    float p = qv * kv;
#pragma unroll
    for (int o = 16; o; o >>= 1) p += __shfl_xor_sync(0xffffffffu, p, o);

    __shared__ float sred[2];
    __shared__ float sf;
    if ((t & 31) == 0) sred[t >> 5] = p;
    __syncthreads();
    if (t == 0) {
        float dot  = (sred[0] + sred[1]) * 0.125f;     // / sqrt(64)
        float fl   = 1.f / (1.f + expf(-sfilt[h * 32 + k]));
        float stim = dot * fl;
        float as    = fabsf(stim);
        float scale = fmaxf(as, 1e-6f);
        float sn    = stim / scale;
        float gate  = 1.f / (1.f + expf(-(as - 0.5f) * 10.f));
        float I     = sn * (0.1f + 0.9f * gate);
        const float alpha = 0.08f;     // DT/TAU = 1/12.5
        const float denom = 1.064f;    // 1 + alpha*B_PARAM
        float v = 0.f, w = 0.f;
#pragma unroll
        for (int it = 0; it < 2; ++it) {
            float dv = v - (v * v * v) / 3.0f - w + I;
            float vn = v + dv;                       // dt = 1
            float wn = (w + (vn + 0.7f) * alpha) / denom;
            v = fminf(fmaxf(vn, -3.f), 3.f);
            w = fminf(fmaxf(wn, -3.f), 3.f);
        }
        sf = v * scale;
    }
    __syncthreads();
    g_vs[(size_t)m * Dq + h * HDq + t] = sf * row[2 * Dq + h * HDq + t];
}

// ======================================================================
// Kernel C: out[b,t,:] = sum_k basis[b,t,k] * y[b*32+k,:]
// thread owns a d-pair; y column slice (32 pairs) lives in registers.
// ======================================================================
__global__ __launch_bounds__(384) void kC(const float* __restrict__ basis,
                                          float* __restrict__ out) {
    const int b = blockIdx.y, seg = blockIdx.x;
    const int tid = threadIdx.x;
    __shared__ ull sb[64][Kq];

    ull yk[Kq];
#pragma unroll
    for (int k = 0; k < Kq; ++k)
        yk[k] = ((const ull*)g_y)[(size_t)(b * Kq + k) * (Dq / 2) + tid];

    const int TSEG = Tq / NSEG;  // 128
    const int t0 = seg * TSEG;
    ull* out2 = (ull*)out + (size_t)b * Tq * (Dq / 2);

    for (int tile = 0; tile < TSEG / 64; ++tile) {
        const int tb = t0 + tile * 64;
        __syncthreads();
        for (int i = tid; i < 64 * Kq; i += 384) {
            int tt = i >> 5, k = i & 31;
            sb[tt][k] = pack2(basis[((size_t)b * Tq + tb + tt) * Kq + k]);
        }
        __syncthreads();
        for (int tt = 0; tt < 64; ++tt) {
            const ulonglong2* bp = (const ulonglong2*)sb[tt];
            ull acc0 = 0ull, acc1 = 0ull;
#pragma unroll
            for (int k2 = 0; k2 < 16; ++k2) {
                ulonglong2 bb = bp[k2];
                acc0 = ffma2(yk[2 * k2],     bb.x, acc0);
                acc1 = ffma2(yk[2 * k2 + 1], bb.y, acc1);
            }
            out2[(size_t)(tb + tt) * (Dq / 2) + tid] = fadd2(acc0, acc1);
        }
    }
}

// ======================================================================
extern "C" void kernel_launch(void* const* d_in, const int* in_sizes, int n_in,
                              void* d_out, int out_size) {
    const float* x     = (const float*)d_in[0];
    const float* basis = (const float*)d_in[1];
    const float* wqkv  = (const float*)d_in[2];
    const float* wout  = (const float*)d_in[3];
    const float* sfilt = (const float*)d_in[4];
    float* out = (float*)d_out;

    kA  <<<dim3(NSEG, Bq), 384>>>(x, basis);
    kA2 <<<(MROWS * Dq) / 256, 256>>>();
    kgemm<<<dim3(2304 / 64, MROWS / 64), 256>>>(wqkv, 3 * Dq, 0);
    kfhn<<<dim3(Hq, MROWS), 64>>>(sfilt);
    kgemm<<<dim3(768 / 64, MROWS / 64), 256>>>(wout, Dq, 1);
    kC  <<<dim3(NSEG, Bq), 384>>>(basis, out);
}

// round 2
// speedup vs baseline: 1.2971x; 1.2971x over previous
#include <cuda_runtime.h>
#include <math.h>

#define Bq 8
#define Tq 4096
#define Dq 768
#define Hq 12
#define HDq 64
#define Kq 32
#define NSEG 32
#define MROWS 256   // B*K

typedef unsigned long long ull;

// ---------- scratch (device globals; no runtime allocation) ----------
__device__ float g_part[(size_t)NSEG * MROWS * Dq];  // T-split partials of xs
__device__ float g_xs  [(size_t)MROWS * Dq];          // xs = basis^T x   [256,768]
__device__ float g_qkv [(size_t)MROWS * 3 * Dq];      // qkv_spec         [256,2304]
__device__ float g_vs  [(size_t)MROWS * Dq];          // fhn-scaled v_spec[256,768]
__device__ float g_y   [(size_t)MROWS * Dq];          // (fhn*v_spec)@Wout^T [256,768]

// ---------- packed f32x2 helpers ----------
__device__ __forceinline__ ull ffma2(ull a, ull b, ull c) {
    ull d;
    asm("fma.rn.f32x2 %0, %1, %2, %3;" : "=l"(d) : "l"(a), "l"(b), "l"(c));
    return d;
}
__device__ __forceinline__ ull fadd2(ull a, ull b) {
    ull d;
    asm("add.rn.f32x2 %0, %1, %2;" : "=l"(d) : "l"(a), "l"(b));
    return d;
}
__device__ __forceinline__ ull pack2(float v) {
    ull r; unsigned u = __float_as_uint(v);
    asm("mov.b64 %0, {%1, %2};" : "=l"(r) : "r"(u), "r"(u));
    return r;
}

// ======================================================================
// Kernel A: partial xs[seg][b,k,d] = sum_{t in seg} basis[b,t,k] * x[b,t,d]
// block = 384 threads, each thread owns a d-pair (f32x2), all 32 k in regs.
// launch_bounds(384,1): 170-reg budget -> acc[32] stays in registers.
// ======================================================================
__global__ __launch_bounds__(384, 1) void kA(const float* __restrict__ x,
                                             const float* __restrict__ basis) {
    const int b = blockIdx.y, seg = blockIdx.x;
    const int tid = threadIdx.x;
    __shared__ ull sb[64][Kq];  // basis values duplicated into f32x2 pairs

    ull acc[Kq];
#pragma unroll
    for (int k = 0; k < Kq; ++k) acc[k] = 0ull;

    const int TSEG = Tq / NSEG;  // 128
    const int t0 = seg * TSEG;
    const ull* x2 = (const ull*)x + (size_t)b * Tq * (Dq / 2);

    for (int tile = 0; tile < TSEG / 64; ++tile) {
        const int tb = t0 + tile * 64;
        __syncthreads();
        for (int i = tid; i < 64 * Kq; i += 384) {
            int tt = i >> 5, k = i & 31;
            sb[tt][k] = pack2(basis[((size_t)b * Tq + tb + tt) * Kq + k]);
        }
        __syncthreads();
        // unroll x2 with prefetch: two t-rows in flight
        ull xv0 = x2[(size_t)tb * (Dq / 2) + tid];
#pragma unroll 4
        for (int tt = 0; tt < 64; tt += 2) {
            ull xv1 = x2[(size_t)(tb + tt + 1) * (Dq / 2) + tid];
            const ulonglong2* bp0 = (const ulonglong2*)sb[tt];
#pragma unroll
            for (int k2 = 0; k2 < 16; ++k2) {
                ulonglong2 bb = bp0[k2];
                acc[2 * k2]     = ffma2(xv0, bb.x, acc[2 * k2]);
                acc[2 * k2 + 1] = ffma2(xv0, bb.y, acc[2 * k2 + 1]);
            }
            if (tt + 2 < 64) xv0 = x2[(size_t)(tb + tt + 2) * (Dq / 2) + tid];
            const ulonglong2* bp1 = (const ulonglong2*)sb[tt + 1];
#pragma unroll
            for (int k2 = 0; k2 < 16; ++k2) {
                ulonglong2 bb = bp1[k2];
                acc[2 * k2]     = ffma2(xv1, bb.x, acc[2 * k2]);
                acc[2 * k2 + 1] = ffma2(xv1, bb.y, acc[2 * k2 + 1]);
            }
        }
    }
    ull* po = (ull*)g_part + ((size_t)seg * MROWS + b * Kq) * (Dq / 2) + tid;
#pragma unroll
    for (int k = 0; k < Kq; ++k) po[(size_t)k * (Dq / 2)] = acc[k];
}

// ======================================================================
// Kernel A2: reduce NSEG partials -> g_xs  (float4 vectorized)
// ======================================================================
__global__ void kA2() {
    const int j = blockIdx.x * 256 + threadIdx.x;  // over MROWS*Dq/4 = 49152
    const float4* p = (const float4*)g_part;
    float4 s = p[j];
#pragma unroll
    for (int seg = 1; seg < NSEG; ++seg) {
        float4 v = p[(size_t)seg * (MROWS * Dq / 4) + j];
        s.x += v.x; s.y += v.y; s.z += v.z; s.w += v.w;
    }
    ((float4*)g_xs)[j] = s;
}

// ======================================================================
// Generic fp32 GEMM  C[M=256,N] = A[256,768] * W[N,768]^T
// 64x64 block tile, 256 threads, 4m x 4n microtile via 8 FFMA2/k-step.
// mode 0: A=g_xs, C=g_qkv ; mode 1: A=g_vs, C=g_y
// ======================================================================
__global__ __launch_bounds__(256, 2) void kgemm(const float* __restrict__ Wm,
                                                int N, int mode) {
    const float* Am = (mode == 0) ? g_xs : g_vs;
    float*       Cm = (mode == 0) ? g_qkv : g_y;

    __shared__ __align__(16) float As[16][64];
    __shared__ __align__(16) float Bs[16][64];

    const int tid = threadIdx.x;
    const int bm = blockIdx.y * 64, bn = blockIdx.x * 64;
    const int tm = (tid >> 4) << 2, tn = (tid & 15) << 2;

    ull acc[4][2];
#pragma unroll
    for (int i = 0; i < 4; ++i) { acc[i][0] = 0ull; acc[i][1] = 0ull; }

    const int lrow = tid >> 2;          // 0..63
    const int lq   = (tid & 3) << 2;    // 0,4,8,12
    const float* Ag = Am + (size_t)(bm + lrow) * 768 + lq;
    const float* Bg = Wm + (size_t)(bn + lrow) * 768 + lq;

    for (int kt = 0; kt < 768; kt += 16) {
        float4 av = *(const float4*)(Ag + kt);
        float4 bv = *(const float4*)(Bg + kt);
        __syncthreads();
        As[lq + 0][lrow] = av.x; As[lq + 1][lrow] = av.y;
        As[lq + 2][lrow] = av.z; As[lq + 3][lrow] = av.w;
        Bs[lq + 0][lrow] = bv.x; Bs[lq + 1][lrow] = bv.y;
        Bs[lq + 2][lrow] = bv.z; Bs[lq + 3][lrow] = bv.w;
        __syncthreads();
#pragma unroll
        for (int k = 0; k < 16; ++k) {
            float4 af = *(const float4*)&As[k][tm];
            ulonglong2 bf = *(const ulonglong2*)&Bs[k][tn];
            ull a0 = pack2(af.x), a1 = pack2(af.y), a2 = pack2(af.z), a3 = pack2(af.w);
            acc[0][0] = ffma2(a0, bf.x, acc[0][0]); acc[0][1] = ffma2(a0, bf.y, acc[0][1]);
            acc[1][0] = ffma2(a1, bf.x, acc[1][0]); acc[1][1] = ffma2(a1, bf.y, acc[1][1]);
            acc[2][0] = ffma2(a2, bf.x, acc[2][0]); acc[2][1] = ffma2(a2, bf.y, acc[2][1]);
            acc[3][0] = ffma2(a3, bf.x, acc[3][0]); acc[3][1] = ffma2(a3, bf.y, acc[3][1]);
        }
    }
#pragma unroll
    for (int i = 0; i < 4; ++i) {
        ulonglong2 r; r.x = acc[i][0]; r.y = acc[i][1];
        *(ulonglong2*)(Cm + (size_t)(bm + tm + i) * N + bn + tn) = r;
    }
}

// ======================================================================
// Kernel B2: attn dot + filter + FHN dynamics + scale v_spec -> g_vs
// one WARP per (m,h); pure shuffle reduction, no smem/syncthreads.
// ======================================================================
__global__ __launch_bounds__(256) void kfhn(const float* __restrict__ sfilt) {
    const int gw = blockIdx.x * 8 + (threadIdx.x >> 5);  // 0..3071
    const int h = gw % Hq;
    const int m = gw / Hq;           // b*32+k
    const int k = m & 31;
    const int l = threadIdx.x & 31;
    const float* row = g_qkv + (size_t)m * (3 * Dq);

    float q0 = row[h * HDq + l],        q1 = row[h * HDq + l + 32];
    float c0 = row[Dq + h * HDq + l],   c1 = row[Dq + h * HDq + l + 32];
    float p = q0 * c0 + q1 * c1;
#pragma unroll
    for (int o = 16; o; o >>= 1) p += __shfl_xor_sync(0xffffffffu, p, o);

    float dot  = p * 0.125f;     // / sqrt(64)
    float fl   = 1.f / (1.f + expf(-sfilt[h * 32 + k]));
    float stim = dot * fl;
    float as    = fabsf(stim);
    float scale = fmaxf(as, 1e-6f);
    float sn    = stim / scale;
    float gate  = 1.f / (1.f + expf(-(as - 0.5f) * 10.f));
    float I     = sn * (0.1f + 0.9f * gate);
    const float alpha = 0.08f;     // DT/TAU = 1/12.5
    const float denom = 1.064f;    // 1 + alpha*B_PARAM
    float v = 0.f, w = 0.f;
#pragma unroll
    for (int it = 0; it < 2; ++it) {
        float dv = v - (v * v * v) / 3.0f - w + I;
        float vn = v + dv;                       // dt = 1
        float wn = (w + (vn + 0.7f) * alpha) / denom;
        v = fminf(fmaxf(vn, -3.f), 3.f);
        w = fminf(fmaxf(wn, -3.f), 3.f);
    }
    float sf = v * scale;

    g_vs[(size_t)m * Dq + h * HDq + l]      = sf * row[2 * Dq + h * HDq + l];
    g_vs[(size_t)m * Dq + h * HDq + l + 32] = sf * row[2 * Dq + h * HDq + l + 32];
}

// ======================================================================
// Kernel C: out[b,t,:] = sum_k basis[b,t,k] * y[b*32+k,:]
// thread owns a d-pair; y column slice (32 pairs) lives in registers.
// ======================================================================
__global__ __launch_bounds__(384, 1) void kC(const float* __restrict__ basis,
                                             float* __restrict__ out) {
    const int b = blockIdx.y, seg = blockIdx.x;
    const int tid = threadIdx.x;
    __shared__ ull sb[64][Kq];

    ull yk[Kq];
#pragma unroll
    for (int k = 0; k < Kq; ++k)
        yk[k] = ((const ull*)g_y)[(size_t)(b * Kq + k) * (Dq / 2) + tid];

    const int TSEG = Tq / NSEG;  // 128
    const int t0 = seg * TSEG;
    ull* out2 = (ull*)out + (size_t)b * Tq * (Dq / 2);

    for (int tile = 0; tile < TSEG / 64; ++tile) {
        const int tb = t0 + tile * 64;
        __syncthreads();
        for (int i = tid; i < 64 * Kq; i += 384) {
            int tt = i >> 5, k = i & 31;
            sb[tt][k] = pack2(basis[((size_t)b * Tq + tb + tt) * Kq + k]);
        }
        __syncthreads();
#pragma unroll 2
        for (int tt = 0; tt < 64; ++tt) {
            const ulonglong2* bp = (const ulonglong2*)sb[tt];
            ull acc0 = 0ull, acc1 = 0ull;
#pragma unroll
            for (int k2 = 0; k2 < 16; ++k2) {
                ulonglong2 bb = bp[k2];
                acc0 = ffma2(yk[2 * k2],     bb.x, acc0);
                acc1 = ffma2(yk[2 * k2 + 1], bb.y, acc1);
            }
            out2[(size_t)(tb + tt) * (Dq / 2) + tid] = fadd2(acc0, acc1);
        }
    }
}

// ======================================================================
extern "C" void kernel_launch(void* const* d_in, const int* in_sizes, int n_in,
                              void* d_out, int out_size) {
    const float* x     = (const float*)d_in[0];
    const float* basis = (const float*)d_in[1];
    const float* wqkv  = (const float*)d_in[2];
    const float* wout  = (const float*)d_in[3];
    const float* sfilt = (const float*)d_in[4];
    float* out = (float*)d_out;

    kA  <<<dim3(NSEG, Bq), 384>>>(x, basis);
    kA2 <<<(MROWS * Dq / 4) / 256, 256>>>();
    kgemm<<<dim3(2304 / 64, MROWS / 64), 256>>>(wqkv, 3 * Dq, 0);
    kfhn<<<3072 / 8, 256>>>(sfilt);
    kgemm<<<dim3(768 / 64, MROWS / 64), 256>>>(wout, Dq, 1);
    kC  <<<dim3(NSEG, Bq), 384>>>(basis, out);
}

// round 3
// speedup vs baseline: 1.4770x; 1.1387x over previous
#include <cuda_runtime.h>
#include <math.h>

#define Bq 8
#define Tq 4096
#define Dq 768
#define Hq 12
#define HDq 64
#define Kq 32
#define NSEG 32
#define MROWS 256   // B*K

typedef unsigned long long ull;

// ---------- scratch (device globals; no runtime allocation) ----------
__device__ float g_part[(size_t)NSEG * MROWS * Dq];   // T-split partials of xs
__device__ float g_xs  [(size_t)MROWS * Dq];           // xs = basis^T x   [256,768]
__device__ float g_qkv [(size_t)MROWS * 3 * Dq];       // qkv_spec         [256,2304]
__device__ float g_vs  [(size_t)MROWS * Dq];           // fhn-scaled v_spec[256,768]
__device__ float g_y   [(size_t)2 * MROWS * Dq];       // split-k partials of y

// ---------- packed f32x2 helpers ----------
__device__ __forceinline__ ull ffma2(ull a, ull b, ull c) {
    ull d;
    asm("fma.rn.f32x2 %0, %1, %2, %3;" : "=l"(d) : "l"(a), "l"(b), "l"(c));
    return d;
}
__device__ __forceinline__ ull fadd2(ull a, ull b) {
    ull d;
    asm("add.rn.f32x2 %0, %1, %2;" : "=l"(d) : "l"(a), "l"(b));
    return d;
}
__device__ __forceinline__ ull pack2(float v) {
    ull r; unsigned u = __float_as_uint(v);
    asm("mov.b64 %0, {%1, %2};" : "=l"(r) : "r"(u), "r"(u));
    return r;
}

// probe kernel: occupies a launch slot so ncu's capture lands on kA
__global__ void kprobe() {}

// ======================================================================
// Kernel A: partial xs[seg][b,k,d] = sum_{t in seg} basis[b,t,k] * x[b,t,d]
// 384 thr: thread = (d-quad 0..191, k-half 0..1). LDG.128 x (2 packed pairs),
// basis pre-packed f32x2 in smem. 4-deep prefetch ring for DRAM latency.
// Per t-row: 1 LDG.128 + 8 LDS.128 + 32 FFMA2  (128 FMA).
// ======================================================================
__global__ __launch_bounds__(384, 1) void kA(const float* __restrict__ x,
                                             const float* __restrict__ basis) {
    const int b = blockIdx.y, seg = blockIdx.x;
    const int tid = threadIdx.x;
    const int dq = tid % 192;          // d-quad (4 floats)
    const int kh = tid / 192;          // warp-uniform (warps 0-5 -> 0, 6-11 -> 1)
    __shared__ ull sb[64][Kq];

    ull acc[32];                       // [0..15]=pair0 over kk, [16..31]=pair1
#pragma unroll
    for (int i = 0; i < 32; ++i) acc[i] = 0ull;

    const int t0 = seg * 128;
    const ulonglong2* x4 = (const ulonglong2*)x + (size_t)b * Tq * 192;

    ulonglong2 xr[4];
#pragma unroll
    for (int j = 0; j < 4; ++j) xr[j] = x4[(size_t)(t0 + j) * 192 + dq];

    for (int tile = 0; tile < 2; ++tile) {
        const int tb = t0 + tile * 64;
        __syncthreads();
#pragma unroll
        for (int i = 0; i < 6; ++i) {          // 384*6 >= 2048
            int idx = tid + i * 384;
            if (idx < 2048) {
                int tt = idx >> 5, k = idx & 31;
                sb[tt][k] = pack2(basis[((size_t)b * Tq + tb + tt) * Kq + k]);
            }
        }
        __syncthreads();
#pragma unroll 2
        for (int t4 = 0; t4 < 16; ++t4) {
#pragma unroll
            for (int j = 0; j < 4; ++j) {
                const int tt = t4 * 4 + j;
                ulonglong2 xv = xr[j];
                int tpf = tb + tt + 4;
                if (tpf > t0 + 127) tpf = t0 + 127;   // clamp: dup load, harmless
                xr[j] = x4[(size_t)tpf * 192 + dq];
                const ulonglong2* bp = (const ulonglong2*)&sb[tt][kh * 16];
#pragma unroll
                for (int kk2 = 0; kk2 < 8; ++kk2) {
                    ulonglong2 bb = bp[kk2];
                    acc[kk2 * 2]          = ffma2(xv.x, bb.x, acc[kk2 * 2]);
                    acc[kk2 * 2 + 1]      = ffma2(xv.x, bb.y, acc[kk2 * 2 + 1]);
                    acc[16 + kk2 * 2]     = ffma2(xv.y, bb.x, acc[16 + kk2 * 2]);
                    acc[16 + kk2 * 2 + 1] = ffma2(xv.y, bb.y, acc[16 + kk2 * 2 + 1]);
                }
            }
        }
    }
    // store: k = kh*16+kk ; floats [4dq .. 4dq+3] as one STG.128
    ulonglong2* po = (ulonglong2*)g_part;
#pragma unroll
    for (int kk = 0; kk < 16; ++kk) {
        int k = kh * 16 + kk;
        ulonglong2 r; r.x = acc[kk]; r.y = acc[16 + kk];
        po[((size_t)seg * MROWS + b * Kq + k) * 192 + dq] = r;
    }
}

// ======================================================================
// Kernel A2: reduce NSEG partials -> g_xs  (float4 vectorized)
// ======================================================================
__global__ void kA2() {
    const int j = blockIdx.x * 256 + threadIdx.x;  // over MROWS*Dq/4
    const float4* p = (const float4*)g_part;
    float4 s = p[j];
#pragma unroll
    for (int seg = 1; seg < NSEG; ++seg) {
        float4 v = p[(size_t)seg * (MROWS * Dq / 4) + j];
        s.x += v.x; s.y += v.y; s.z += v.z; s.w += v.w;
    }
    ((float4*)g_xs)[j] = s;
}

// ======================================================================
// GEMM  C[M=256,N] = A[256,768] * W[N,768]^T   (range [k0,k1) via blockIdx.z)
// 64x64 tile, 256 thr, 4m x 4n microtile. A pre-packed (f32x2) in smem:
// per k-step 3 LDS.128 + 8 FFMA2.
// mode 0: A=g_xs -> g_qkv (z=0 full K). mode 1: A=g_vs -> g_y[z] (split-K).
// ======================================================================
__global__ __launch_bounds__(256, 2) void kgemm(const float* __restrict__ Wm,
                                                int N, int mode, int ks) {
    const int z = blockIdx.z;
    const float* Am = (mode == 0) ? g_xs : g_vs;
    float*       Cm = (mode == 0) ? g_qkv : (g_y + (size_t)z * MROWS * Dq);

    __shared__ __align__(16) ull   Asu[16][64];
    __shared__ __align__(16) float Bs [16][64];

    const int tid = threadIdx.x;
    const int bm = blockIdx.y * 64, bn = blockIdx.x * 64;
    const int tm = (tid >> 4) << 2, tn = (tid & 15) << 2;
    const int k0 = z * ks, k1 = k0 + ks;

    ull acc[4][2];
#pragma unroll
    for (int i = 0; i < 4; ++i) { acc[i][0] = 0ull; acc[i][1] = 0ull; }

    const int lrow = tid >> 2;          // 0..63
    const int lq   = (tid & 3) << 2;    // 0,4,8,12
    const float* Ag = Am + (size_t)(bm + lrow) * 768 + lq;
    const float* Bg = Wm + (size_t)(bn + lrow) * 768 + lq;

    for (int kt = k0; kt < k1; kt += 16) {
        float4 av = *(const float4*)(Ag + kt);
        float4 bv = *(const float4*)(Bg + kt);
        __syncthreads();
        Asu[lq + 0][lrow] = pack2(av.x); Asu[lq + 1][lrow] = pack2(av.y);
        Asu[lq + 2][lrow] = pack2(av.z); Asu[lq + 3][lrow] = pack2(av.w);
        Bs[lq + 0][lrow] = bv.x; Bs[lq + 1][lrow] = bv.y;
        Bs[lq + 2][lrow] = bv.z; Bs[lq + 3][lrow] = bv.w;
        __syncthreads();
#pragma unroll
        for (int k = 0; k < 16; ++k) {
            ulonglong2 a01 = *(const ulonglong2*)&Asu[k][tm];
            ulonglong2 a23 = *(const ulonglong2*)&Asu[k][tm + 2];
            ulonglong2 bf  = *(const ulonglong2*)&Bs[k][tn];
            acc[0][0] = ffma2(a01.x, bf.x, acc[0][0]); acc[0][1] = ffma2(a01.x, bf.y, acc[0][1]);
            acc[1][0] = ffma2(a01.y, bf.x, acc[1][0]); acc[1][1] = ffma2(a01.y, bf.y, acc[1][1]);
            acc[2][0] = ffma2(a23.x, bf.x, acc[2][0]); acc[2][1] = ffma2(a23.x, bf.y, acc[2][1]);
            acc[3][0] = ffma2(a23.y, bf.x, acc[3][0]); acc[3][1] = ffma2(a23.y, bf.y, acc[3][1]);
        }
    }
#pragma unroll
    for (int i = 0; i < 4; ++i) {
        ulonglong2 r; r.x = acc[i][0]; r.y = acc[i][1];
        *(ulonglong2*)(Cm + (size_t)(bm + tm + i) * N + bn + tn) = r;
    }
}

// ======================================================================
// FHN: one WARP per (m,h); shuffle reduction only.
// ======================================================================
__global__ __launch_bounds__(256) void kfhn(const float* __restrict__ sfilt) {
    const int gw = blockIdx.x * 8 + (threadIdx.x >> 5);  // 0..3071
    const int h = gw % Hq;
    const int m = gw / Hq;           // b*32+k
    const int k = m & 31;
    const int l = threadIdx.x & 31;
    const float* row = g_qkv + (size_t)m * (3 * Dq);

    float q0 = row[h * HDq + l],        q1 = row[h * HDq + l + 32];
    float c0 = row[Dq + h * HDq + l],   c1 = row[Dq + h * HDq + l + 32];
    float p = q0 * c0 + q1 * c1;
#pragma unroll
    for (int o = 16; o; o >>= 1) p += __shfl_xor_sync(0xffffffffu, p, o);

    float dot  = p * 0.125f;
    float fl   = 1.f / (1.f + expf(-sfilt[h * 32 + k]));
    float stim = dot * fl;
    float as    = fabsf(stim);
    float scale = fmaxf(as, 1e-6f);
    float sn    = stim / scale;
    float gate  = 1.f / (1.f + expf(-(as - 0.5f) * 10.f));
    float I     = sn * (0.1f + 0.9f * gate);
    const float alpha = 0.08f;
    const float denom = 1.064f;
    float v = 0.f, w = 0.f;
#pragma unroll
    for (int it = 0; it < 2; ++it) {
        float dv = v - (v * v * v) / 3.0f - w + I;
        float vn = v + dv;
        float wn = (w + (vn + 0.7f) * alpha) / denom;
        v = fminf(fmaxf(vn, -3.f), 3.f);
        w = fminf(fmaxf(wn, -3.f), 3.f);
    }
    float sf = v * scale;

    g_vs[(size_t)m * Dq + h * HDq + l]      = sf * row[2 * Dq + h * HDq + l];
    g_vs[(size_t)m * Dq + h * HDq + l + 32] = sf * row[2 * Dq + h * HDq + l + 32];
}

// ======================================================================
// Kernel C: out[b,t,:] = sum_k basis[b,t,k] * y[b*32+k,:]
// thread owns a d-pair; y (sum of 2 split-k partials) in registers.
// ======================================================================
__global__ __launch_bounds__(384, 1) void kC(const float* __restrict__ basis,
                                             float* __restrict__ out) {
    const int b = blockIdx.y, seg = blockIdx.x;
    const int tid = threadIdx.x;
    __shared__ ull sb[64][Kq];

    ull yk[Kq];
#pragma unroll
    for (int k = 0; k < Kq; ++k) {
        size_t idx = (size_t)(b * Kq + k) * (Dq / 2) + tid;
        yk[k] = fadd2(((const ull*)g_y)[idx],
                      ((const ull*)g_y)[(size_t)MROWS * (Dq / 2) + idx]);
    }

    const int t0 = seg * 128;
    ull* out2 = (ull*)out + (size_t)b * Tq * (Dq / 2);

    for (int tile = 0; tile < 2; ++tile) {
        const int tb = t0 + tile * 64;
        __syncthreads();
#pragma unroll
        for (int i = 0; i < 6; ++i) {
            int idx = tid + i * 384;
            if (idx < 2048) {
                int tt = idx >> 5, k = idx & 31;
                sb[tt][k] = pack2(basis[((size_t)b * Tq + tb + tt) * Kq + k]);
            }
        }
        __syncthreads();
#pragma unroll 2
        for (int tt = 0; tt < 64; ++tt) {
            const ulonglong2* bp = (const ulonglong2*)sb[tt];
            ull acc0 = 0ull, acc1 = 0ull;
#pragma unroll
            for (int k2 = 0; k2 < 16; ++k2) {
                ulonglong2 bb = bp[k2];
                acc0 = ffma2(yk[2 * k2],     bb.x, acc0);
                acc1 = ffma2(yk[2 * k2 + 1], bb.y, acc1);
            }
            out2[(size_t)(tb + tt) * (Dq / 2) + tid] = fadd2(acc0, acc1);
        }
    }
}

// ======================================================================
extern "C" void kernel_launch(void* const* d_in, const int* in_sizes, int n_in,
                              void* d_out, int out_size) {
    const float* x     = (const float*)d_in[0];
    const float* basis = (const float*)d_in[1];
    const float* wqkv  = (const float*)d_in[2];
    const float* wout  = (const float*)d_in[3];
    const float* sfilt = (const float*)d_in[4];
    float* out = (float*)d_out;

    kprobe<<<1, 1>>>();
    kprobe<<<1, 1>>>();
    kprobe<<<1, 1>>>();
    kA  <<<dim3(NSEG, Bq), 384>>>(x, basis);                 // 4th launch -> ncu
    kA2 <<<(MROWS * Dq / 4) / 256, 256>>>();
    kgemm<<<dim3(2304 / 64, MROWS / 64, 1), 256>>>(wqkv, 3 * Dq, 0, 768);
    kfhn<<<3072 / 8, 256>>>(sfilt);
    kgemm<<<dim3(768 / 64, MROWS / 64, 2), 256>>>(wout, Dq, 1, 384);
    kC  <<<dim3(NSEG, Bq), 384>>>(basis, out);
}

// round 9
// speedup vs baseline: 1.8110x; 1.2262x over previous
#include <cuda_runtime.h>
#include <math.h>

#define Bq 8
#define Tq 4096
#define Dq 768
#define Hq 12
#define HDq 64
#define Kq 32
#define NSEG 16
#define MROWS 256   // B*K

typedef unsigned long long ull;

// ---------- scratch ----------
__device__ float g_part[(size_t)NSEG * MROWS * Dq];
__device__ float g_xs  [(size_t)MROWS * Dq];
__device__ float g_qkv [(size_t)MROWS * 3 * Dq];
__device__ float g_vs  [(size_t)MROWS * Dq];
__device__ float g_y   [(size_t)3 * MROWS * Dq];   // split-k partials
__device__ float g_ysum[(size_t)MROWS * Dq];

// ---------- packed f32x2 helpers ----------
__device__ __forceinline__ ull ffma2(ull a, ull b, ull c) {
    ull d;
    asm("fma.rn.f32x2 %0, %1, %2, %3;" : "=l"(d) : "l"(a), "l"(b), "l"(c));
    return d;
}
__device__ __forceinline__ ull fadd2(ull a, ull b) {
    ull d;
    asm("add.rn.f32x2 %0, %1, %2;" : "=l"(d) : "l"(a), "l"(b));
    return d;
}
__device__ __forceinline__ ull pack2(float v) {
    ull r; unsigned u = __float_as_uint(v);
    asm("mov.b64 %0, {%1, %2};" : "=l"(r) : "r"(u), "r"(u));
    return r;
}

__global__ void kprobe() {}

// ======================================================================
// kA: partial xs[seg][b,k,d] = sum_{t in seg} basis[b,t,k] * x[b,t,d]
// 768 thr = (dq 0..191 d-quad) x (kh 0..3, 8 k each). acc = 16 ull.
// 24 warps/SM, 128 blocks = 1 wave. Per t-row: 1 LDG.128 + 4 LDS.128 + 16 FFMA2.
// ======================================================================
__global__ __launch_bounds__(768, 1) void kA(const float* __restrict__ x,
                                             const float* __restrict__ basis) {
    const int b = blockIdx.y, seg = blockIdx.x;
    const int tid = threadIdx.x;
    const int dq = tid % 192;
    const int kh = tid / 192;          // warp-uniform
    __shared__ ull sb[64][Kq];

    ull acc[16];
#pragma unroll
    for (int i = 0; i < 16; ++i) acc[i] = 0ull;

    const int t0 = seg * 256;          // TSEG = 256
    const ulonglong2* x4 = (const ulonglong2*)x + (size_t)b * Tq * 192;

    ulonglong2 xr[2];
    xr[0] = x4[(size_t)t0 * 192 + dq];
    xr[1] = x4[(size_t)(t0 + 1) * 192 + dq];

    for (int tile = 0; tile < 4; ++tile) {
        const int tb = t0 + tile * 64;
        __syncthreads();
#pragma unroll
        for (int i = 0; i < 3; ++i) {
            int idx = tid + i * 768;
            if (idx < 2048) {
                int tt = idx >> 5, k = idx & 31;
                sb[tt][k] = pack2(basis[((size_t)b * Tq + tb + tt) * Kq + k]);
            }
        }
        __syncthreads();
#pragma unroll 4
        for (int t2 = 0; t2 < 32; ++t2) {
#pragma unroll
            for (int j = 0; j < 2; ++j) {
                const int tt = t2 * 2 + j;
                ulonglong2 xv = xr[j];
                int tpf = tb + tt + 2;
                if (tpf > t0 + 255) tpf = t0 + 255;   // dup load at seg end: harmless
                xr[j] = x4[(size_t)tpf * 192 + dq];
                const ulonglong2* bp = (const ulonglong2*)&sb[tt][kh * 8];
#pragma unroll
                for (int kk2 = 0; kk2 < 4; ++kk2) {
                    ulonglong2 bb = bp[kk2];
                    acc[kk2 * 2]         = ffma2(xv.x, bb.x, acc[kk2 * 2]);
                    acc[kk2 * 2 + 1]     = ffma2(xv.x, bb.y, acc[kk2 * 2 + 1]);
                    acc[8 + kk2 * 2]     = ffma2(xv.y, bb.x, acc[8 + kk2 * 2]);
                    acc[8 + kk2 * 2 + 1] = ffma2(xv.y, bb.y, acc[8 + kk2 * 2 + 1]);
                }
            }
        }
    }
    ulonglong2* po = (ulonglong2*)g_part;
#pragma unroll
    for (int kk = 0; kk < 8; ++kk) {
        int k = kh * 8 + kk;
        ulonglong2 r; r.x = acc[kk]; r.y = acc[8 + kk];
        po[((size_t)seg * MROWS + b * Kq + k) * 192 + dq] = r;
    }
}

// ======================================================================
// kA2: reduce NSEG partials -> g_xs
// ======================================================================
__global__ void kA2() {
    const int j = blockIdx.x * 256 + threadIdx.x;
    const float4* p = (const float4*)g_part;
    float4 s = p[j];
#pragma unroll
    for (int seg = 1; seg < NSEG; ++seg) {
        float4 v = p[(size_t)seg * (MROWS * Dq / 4) + j];
        s.x += v.x; s.y += v.y; s.z += v.z; s.w += v.w;
    }
    ((float4*)g_xs)[j] = s;
}

// ======================================================================
// GEMM  C[M=256,N] = A[256,768] * W[N,768]^T  (K range via blockIdx.z)
// 64x64 tile, 256 thr, LDG prefetched ahead of compute.
// ======================================================================
__global__ __launch_bounds__(256, 2) void kgemm(const float* __restrict__ Wm,
                                                int N, int mode, int ks) {
    const int z = blockIdx.z;
    const float* Am = (mode == 0) ? g_xs : g_vs;
    float*       Cm = (mode == 0) ? g_qkv : (g_y + (size_t)z * MROWS * Dq);

    __shared__ __align__(16) ull   Asu[16][64];
    __shared__ __align__(16) float Bs [16][64];

    const int tid = threadIdx.x;
    const int bm = blockIdx.y * 64, bn = blockIdx.x * 64;
    const int tm = (tid >> 4) << 2, tn = (tid & 15) << 2;
    const int k0 = z * ks, k1 = k0 + ks;

    ull acc[4][2];
#pragma unroll
    for (int i = 0; i < 4; ++i) { acc[i][0] = 0ull; acc[i][1] = 0ull; }

    const int lrow = tid >> 2;
    const int lq   = (tid & 3) << 2;
    const float* Ag = Am + (size_t)(bm + lrow) * 768 + lq;
    const float* Bg = Wm + (size_t)(bn + lrow) * 768 + lq;

    float4 av = *(const float4*)(Ag + k0);
    float4 bv = *(const float4*)(Bg + k0);

    for (int kt = k0; kt < k1; kt += 16) {
        __syncthreads();
        Asu[lq + 0][lrow] = pack2(av.x); Asu[lq + 1][lrow] = pack2(av.y);
        Asu[lq + 2][lrow] = pack2(av.z); Asu[lq + 3][lrow] = pack2(av.w);
        Bs[lq + 0][lrow] = bv.x; Bs[lq + 1][lrow] = bv.y;
        Bs[lq + 2][lrow] = bv.z; Bs[lq + 3][lrow] = bv.w;
        __syncthreads();
        if (kt + 16 < k1) {                    // prefetch hides behind compute
            av = *(const float4*)(Ag + kt + 16);
            bv = *(const float4*)(Bg + kt + 16);
        }
#pragma unroll
        for (int k = 0; k < 16; ++k) {
            ulonglong2 a01 = *(const ulonglong2*)&Asu[k][tm];
            ulonglong2 a23 = *(const ulonglong2*)&Asu[k][tm + 2];
            ulonglong2 bf  = *(const ulonglong2*)&Bs[k][tn];
            acc[0][0] = ffma2(a01.x, bf.x, acc[0][0]); acc[0][1] = ffma2(a01.x, bf.y, acc[0][1]);
            acc[1][0] = ffma2(a01.y, bf.x, acc[1][0]); acc[1][1] = ffma2(a01.y, bf.y, acc[1][1]);
            acc[2][0] = ffma2(a23.x, bf.x, acc[2][0]); acc[2][1] = ffma2(a23.x, bf.y, acc[2][1]);
            acc[3][0] = ffma2(a23.y, bf.x, acc[3][0]); acc[3][1] = ffma2(a23.y, bf.y, acc[3][1]);
        }
    }
#pragma unroll
    for (int i = 0; i < 4; ++i) {
        ulonglong2 r; r.x = acc[i][0]; r.y = acc[i][1];
        *(ulonglong2*)(Cm + (size_t)(bm + tm + i) * N + bn + tn) = r;
    }
}

// ======================================================================
// FHN: one warp per (m,h)
// ======================================================================
__global__ __launch_bounds__(256) void kfhn(const float* __restrict__ sfilt) {
    const int gw = blockIdx.x * 8 + (threadIdx.x >> 5);
    const int h = gw % Hq;
    const int m = gw / Hq;
    const int k = m & 31;
    const int l = threadIdx.x & 31;
    const float* row = g_qkv + (size_t)m * (3 * Dq);

    float q0 = row[h * HDq + l],      q1 = row[h * HDq + l + 32];
    float c0 = row[Dq + h * HDq + l], c1 = row[Dq + h * HDq + l + 32];
    float p = q0 * c0 + q1 * c1;
#pragma unroll
    for (int o = 16; o; o >>= 1) p += __shfl_xor_sync(0xffffffffu, p, o);

    float dot  = p * 0.125f;
    float fl   = 1.f / (1.f + expf(-sfilt[h * 32 + k]));
    float stim = dot * fl;
    float as    = fabsf(stim);
    float scale = fmaxf(as, 1e-6f);
    float sn    = stim / scale;
    float gate  = 1.f / (1.f + expf(-(as - 0.5f) * 10.f));
    float I     = sn * (0.1f + 0.9f * gate);
    const float alpha = 0.08f, denom = 1.064f;
    float v = 0.f, w = 0.f;
#pragma unroll
    for (int it = 0; it < 2; ++it) {
        float dv = v - (v * v * v) / 3.0f - w + I;
        float vn = v + dv;
        float wn = (w + (vn + 0.7f) * alpha) / denom;
        v = fminf(fmaxf(vn, -3.f), 3.f);
        w = fminf(fmaxf(wn, -3.f), 3.f);
    }
    float sf = v * scale;

    g_vs[(size_t)m * Dq + h * HDq + l]      = sf * row[2 * Dq + h * HDq + l];
    g_vs[(size_t)m * Dq + h * HDq + l + 32] = sf * row[2 * Dq + h * HDq + l + 32];
}

// ======================================================================
// kyr: sum 3 split-k partials -> g_ysum
// ======================================================================
__global__ void kyr() {
    const int j = blockIdx.x * 256 + threadIdx.x;
    const float4* p = (const float4*)g_y;
    float4 a = p[j], bb = p[j + MROWS * Dq / 4], c = p[j + 2 * (MROWS * Dq / 4)];
    float4 s; s.x = a.x + bb.x + c.x; s.y = a.y + bb.y + c.y;
    s.z = a.z + bb.z + c.z; s.w = a.w + bb.w + c.w;
    ((float4*)g_ysum)[j] = s;
}

// ======================================================================
// kC as GEMM: out[b][t, d] = sum_k basis[b][t,k] * ysum[b*32+k, d]
// Tile 64t x 128d, 128 thr, microtile 4t x 16d (d strided by 32 floats).
// Row pad = 66 ulls (EVEN -> every row 16B-aligned; round-4 bug was 65).
// ======================================================================
__global__ __launch_bounds__(128) void kC(const float* __restrict__ basis,
                                          float* __restrict__ out) {
    const int bn = blockIdx.x * 128;   // d
    const int bt = blockIdx.y * 64;    // t
    const int b  = blockIdx.z;
    const int tid = threadIdx.x;
    const int tr = tid >> 3;           // 0..15 -> t = tr*4
    const int tc = tid & 7;            // 0..7  -> d groups tc*4 + j*32

    __shared__ __align__(16) ull sA[32][66];   // [k][t] packed basis
    __shared__ __align__(16) ull sB[32][66];   // [k][d-pair] packed y

#pragma unroll
    for (int i = 0; i < 4; ++i) {
        int idx = tid + i * 128;                 // 0..511
        int row = idx >> 3, c4 = idx & 7;
        float4 f = *(const float4*)&basis[((size_t)b * Tq + bt + row) * Kq + c4 * 4];
        sA[c4 * 4 + 0][row] = pack2(f.x);
        sA[c4 * 4 + 1][row] = pack2(f.y);
        sA[c4 * 4 + 2][row] = pack2(f.z);
        sA[c4 * 4 + 3][row] = pack2(f.w);
    }
#pragma unroll
    for (int i = 0; i < 8; ++i) {
        int idx = tid + i * 128;                 // 0..1023
        int k = idx >> 5, g = idx & 31;          // g = 4-float group
        ulonglong2 v = *(const ulonglong2*)&g_ysum[(size_t)(b * Kq + k) * Dq + bn + g * 4];
        sB[k][g * 2]     = v.x;
        sB[k][g * 2 + 1] = v.y;
    }
    __syncthreads();

    ull acc[4][8];
#pragma unroll
    for (int i = 0; i < 4; ++i)
#pragma unroll
        for (int j = 0; j < 8; ++j) acc[i][j] = 0ull;

#pragma unroll
    for (int k = 0; k < 32; ++k) {
        ulonglong2 a01 = *(const ulonglong2*)&sA[k][tr * 4];
        ulonglong2 a23 = *(const ulonglong2*)&sA[k][tr * 4 + 2];
        ulonglong2 b0 = *(const ulonglong2*)&sB[k][tc * 2];
        ulonglong2 b1 = *(const ulonglong2*)&sB[k][tc * 2 + 16];
        ulonglong2 b2 = *(const ulonglong2*)&sB[k][tc * 2 + 32];
        ulonglong2 b3 = *(const ulonglong2*)&sB[k][tc * 2 + 48];
        ull a[4] = {a01.x, a01.y, a23.x, a23.y};
#pragma unroll
        for (int i = 0; i < 4; ++i) {
            acc[i][0] = ffma2(a[i], b0.x, acc[i][0]);
            acc[i][1] = ffma2(a[i], b0.y, acc[i][1]);
            acc[i][2] = ffma2(a[i], b1.x, acc[i][2]);
            acc[i][3] = ffma2(a[i], b1.y, acc[i][3]);
            acc[i][4] = ffma2(a[i], b2.x, acc[i][4]);
            acc[i][5] = ffma2(a[i], b2.y, acc[i][5]);
            acc[i][6] = ffma2(a[i], b3.x, acc[i][6]);
            acc[i][7] = ffma2(a[i], b3.y, acc[i][7]);
        }
    }

#pragma unroll
    for (int i = 0; i < 4; ++i) {
        float* base = out + ((size_t)b * Tq + bt + tr * 4 + i) * Dq + bn + tc * 4;
#pragma unroll
        for (int j = 0; j < 4; ++j) {
            ulonglong2 r; r.x = acc[i][2 * j]; r.y = acc[i][2 * j + 1];
            *(ulonglong2*)(base + j * 32) = r;
        }
    }
}

// ======================================================================
extern "C" void kernel_launch(void* const* d_in, const int* in_sizes, int n_in,
                              void* d_out, int out_size) {
    const float* x     = (const float*)d_in[0];
    const float* basis = (const float*)d_in[1];
    const float* wqkv  = (const float*)d_in[2];
    const float* wout  = (const float*)d_in[3];
    const float* sfilt = (const float*)d_in[4];
    float* out = (float*)d_out;

    kprobe<<<1, 1>>>();
    kprobe<<<1, 1>>>();
    kprobe<<<1, 1>>>();
    kA  <<<dim3(NSEG, Bq), 768>>>(x, basis);
    kA2 <<<(MROWS * Dq / 4) / 256, 256>>>();
    kgemm<<<dim3(2304 / 64, MROWS / 64, 1), 256>>>(wqkv, 3 * Dq, 0, 768);
    kfhn<<<3072 / 8, 256>>>(sfilt);
    kgemm<<<dim3(768 / 64, MROWS / 64, 3), 256>>>(wout, Dq, 1, 256);
    kyr <<<(MROWS * Dq / 4) / 256, 256>>>();
    kC  <<<dim3(Dq / 128, Tq / 64, Bq), 128>>>(basis, out);
}